// round 6
// baseline (speedup 1.0000x reference)
#include <cuda_runtime.h>
#include <cuda_fp16.h>
#include <cstdint>

#define BSZ 32
#define CIc 32
#define PP  256

__device__ short g_votes[BSZ*32*CIc*8*PP];   // [b][co][ci][no][p], value*256 (exact)
__device__ float g_logits[BSZ*CIc*32*PP];    // [b][ci][co][p]
__device__ float g_smax[BSZ*CIc];
__device__ float g_ssum[BSZ*CIc];

// ---------------- helpers ----------------
static __device__ __forceinline__ uint32_t smem_u32(const void* p) {
    uint32_t a;
    asm("{ .reg .u64 t; cvta.to.shared.u64 t, %1; cvt.u32.u64 %0, t; }" : "=r"(a) : "l"(p));
    return a;
}

#define MMA16816(d, a, b) \
    asm volatile("mma.sync.aligned.m16n8k16.row.col.f32.f16.f16.f32 " \
        "{%0,%1,%2,%3}, {%4,%5,%6,%7}, {%8,%9}, {%0,%1,%2,%3};" \
        : "+f"((d)[0]), "+f"((d)[1]), "+f"((d)[2]), "+f"((d)[3]) \
        : "r"((a)[0]), "r"((a)[1]), "r"((a)[2]), "r"((a)[3]), "r"((b)[0]), "r"((b)[1]))

#define LDMX4(r0, r1, r2, r3, addr) \
    asm volatile("ldmatrix.sync.aligned.m8n8.x4.shared.b16 {%0,%1,%2,%3}, [%4];" \
        : "=r"(r0), "=r"(r1), "=r"(r2), "=r"(r3) : "r"(addr))

static __device__ __forceinline__ uint32_t packh(__half a, __half b) {
    return (uint32_t)__half_as_ushort(a) | ((uint32_t)__half_as_ushort(b) << 16);
}
// rn fp16 2-term split of a float pair; returns hi pair, writes lo pair.
static __device__ __forceinline__ uint32_t packsplit(float f0, float f1, uint32_t &lo) {
    __half h0 = __float2half_rn(f0), h1 = __float2half_rn(f1);
    __half l0 = __float2half_rn(__fsub_rn(f0, __half2float(h0)));
    __half l1 = __float2half_rn(__fsub_rn(f1, __half2float(h1)));
    lo = packh(l0, l1);
    return packh(h0, h1);
}

// smem layout (bytes): 160B rows (80 fp16 k-slots, 72 real + 8 pad)
#define BHI_OFF    0u         // [256 o][160B]
#define BLO_OFF    40960u
#define AHI_OFF    81920u     // [256 p][160B]
#define ALO_OFF    122880u
#define STG_OFF    163840u    // 8 warps * 64o*40p shorts = 40960 (x tile aliased here)
#define CBS_OFF    204800u
#define A1S_OFF    205824u
#define KLUT_OFF   206848u
#define CONV_SMEM  207232

// ---------------------------------------------------------------------------
// Kernel 1: fp16-split mma.sync conv -> int16 votes + iteration-1 logits.
// block = (b, ci): D[256p, 256o] = X[256,72] * W^T, K padded to 80.
// A and B both in smem as fp16 hi/lo; fragments via ldmatrix (no spills).
// ---------------------------------------------------------------------------
__global__ void __launch_bounds__(256, 1) conv_votes_kernel(
    const float* __restrict__ x, const float* __restrict__ w,
    const float* __restrict__ cb, const float* __restrict__ bias)
{
    extern __shared__ char sh[];
    float* xs  = (float*)(sh + STG_OFF);    // aliased: x pad tile, dead before staging
    float* cbs = (float*)(sh + CBS_OFF);
    int*   a1s = (int*)(sh + A1S_OFF);
    int*   klut= (int*)(sh + KLUT_OFF);
    const uint32_t smb = smem_u32(sh);

    const int t = threadIdx.x;
    const int wid = t >> 5, lane = t & 31;
    const int b = blockIdx.x >> 5, ci = blockIdx.x & 31;

    // --- fills ---
    for (int i = t; i < 2592; i += 256) xs[i] = 0.f;
    cbs[t] = cb[t];
    if (t < 72) { int ni = t/9, r = t%9; klut[t] = ni*324 + (r/3)*18 + (r%3); }
    if (t < 32) {   // iteration-1 activation from bias (quant(route)==0)
        float pv[8]; float ss = 0.f;
        #pragma unroll
        for (int no = 0; no < 8; no++) {
            float q = rintf(__fmul_rn(bias[t*8+no], 256.f)) * 0.00390625f;
            pv[no] = q; ss = __fadd_rn(ss, __fmul_rn(q, q));
        }
        float n = sqrtf(ss);
        float den = __fadd_rn(1.f, __fmul_rn(n, n));
        #pragma unroll
        for (int no = 0; no < 8; no++) {
            float a = __fdiv_rn(__fmul_rn(pv[no], n), den);
            a1s[t*8+no] = __float2int_rn(__fmul_rn(a, 256.f));
        }
    }
    // B fill: this thread's o = t; W row -> hi/lo fp16, 160B rows
    {
        const float4* wr = (const float4*)(w + t*72);
        char* bh = sh + BHI_OFF + t*160;
        char* bl = sh + BLO_OFF + t*160;
        #pragma unroll
        for (int q = 0; q < 18; q++) {
            float4 v = wr[q];
            uint32_t l0, l1;
            uint32_t h0 = packsplit(v.x, v.y, l0);
            uint32_t h1 = packsplit(v.z, v.w, l1);
            *(uint2*)(bh + q*8) = make_uint2(h0, h1);
            *(uint2*)(bl + q*8) = make_uint2(l0, l1);
        }
        *(uint4*)(bh + 144) = make_uint4(0,0,0,0);   // k pad 72..79
        *(uint4*)(bl + 144) = make_uint4(0,0,0,0);
    }
    __syncthreads();
    {   // x interior (zeros already placed for halo)
        const float* xb = x + (b*CIc + ci)*8*PP;
        #pragma unroll
        for (int i = 0; i < 8; i++) {
            int idx = t + i*256;
            int ni = idx >> 8, rem = idx & 255;
            xs[ni*324 + ((rem>>4)+1)*18 + (rem&15) + 1] = xb[idx];
        }
    }
    __syncthreads();
    // A fill: this thread's p = t; im2col row -> hi/lo fp16, 160B rows
    {
        const int xyb = (t >> 4)*18 + (t & 15);
        char* ah = sh + AHI_OFF + t*160;
        char* al = sh + ALO_OFF + t*160;
        #pragma unroll
        for (int q = 0; q < 9; q++) {       // 9*8 = 72 real k
            uint32_t h[4], l[4];
            #pragma unroll
            for (int j = 0; j < 4; j++) {
                int k0 = q*8 + 2*j;
                float f0 = xs[klut[k0]   + xyb];
                float f1 = xs[klut[k0+1] + xyb];
                h[j] = packsplit(f0, f1, l[j]);
            }
            *(uint4*)(ah + q*16) = make_uint4(h[0], h[1], h[2], h[3]);
            *(uint4*)(al + q*16) = make_uint4(l[0], l[1], l[2], l[3]);
        }
        *(uint4*)(ah + 144) = make_uint4(0,0,0,0);
        *(uint4*)(al + 144) = make_uint4(0,0,0,0);
    }
    __syncthreads();   // also: xs (stage alias) dead from here

    const int wrow = wid*32;
    const int lane2 = (lane & 3)*2;
    short* stg = (short*)(sh + STG_OFF) + wid*2560;   // [64 o][40 p-pad] shorts

    #pragma unroll 1
    for (int pass = 0; pass < 4; pass++) {
        float acc[2][8][4];
        #pragma unroll
        for (int mt = 0; mt < 2; mt++)
            #pragma unroll
            for (int nt = 0; nt < 8; nt++)
                #pragma unroll
                for (int j = 0; j < 4; j++) acc[mt][nt][j] = 0.f;

        #pragma unroll
        for (int kc = 0; kc < 5; kc++) {
            // A fragments via ldmatrix (row-major [p][k])
            uint32_t ah[2][4], al2[2][4];
            #pragma unroll
            for (int mt = 0; mt < 2; mt++) {
                const uint32_t arow = wrow + mt*16 + (lane & 15);
                const uint32_t aoff = arow*160 + kc*32 + ((lane >> 4) << 4);
                LDMX4(ah[mt][0], ah[mt][1], ah[mt][2], ah[mt][3], smb + AHI_OFF + aoff);
                LDMX4(al2[mt][0], al2[mt][1], al2[mt][2], al2[mt][3], smb + ALO_OFF + aoff);
            }
            // B fragments via ldmatrix ([o][k] rows)
            uint32_t bh[8][2], bl[8][2];
            #pragma unroll
            for (int g = 0; g < 4; g++) {
                const uint32_t row = pass*64 + g*16 + (lane & 7) + ((lane >> 4) << 3);
                const uint32_t koff = kc*32 + ((lane >> 3) & 1)*16;
                LDMX4(bh[2*g][0], bh[2*g][1], bh[2*g+1][0], bh[2*g+1][1],
                      smb + BHI_OFF + row*160 + koff);
                LDMX4(bl[2*g][0], bl[2*g][1], bl[2*g+1][0], bl[2*g+1][1],
                      smb + BLO_OFF + row*160 + koff);
            }
            #pragma unroll
            for (int mt = 0; mt < 2; mt++)
                #pragma unroll
                for (int nt = 0; nt < 8; nt++) {
                    MMA16816(acc[mt][nt], ah[mt], bh[nt]);
                    MMA16816(acc[mt][nt], ah[mt], bl[nt]);
                    MMA16816(acc[mt][nt], al2[mt], bh[nt]);
                }
        }

        // --- epilogue: quantize, stage transposed [o][p], then wide stores ---
        #pragma unroll
        for (int mt = 0; mt < 2; mt++) {
            const int r = (lane >> 2) + mt*16;
            #pragma unroll
            for (int nt = 0; nt < 8; nt++) {
                const int c = nt*8 + lane2;
                const int o0 = pass*64 + c;
                int v0 = __float2int_rn((acc[mt][nt][0] + cbs[o0])   * 256.f);
                int v1 = __float2int_rn((acc[mt][nt][1] + cbs[o0+1]) * 256.f);
                int v2 = __float2int_rn((acc[mt][nt][2] + cbs[o0])   * 256.f);
                int v3 = __float2int_rn((acc[mt][nt][3] + cbs[o0+1]) * 256.f);
                stg[c*40 + r]         = (short)v0;
                stg[(c+1)*40 + r]     = (short)v1;
                stg[c*40 + r + 8]     = (short)v2;
                stg[(c+1)*40 + r + 8] = (short)v3;
            }
        }
        __syncwarp();

        // votes out: uint4 = 8 consecutive p
        #pragma unroll
        for (int i = 0; i < 8; i++) {
            const int task = i*32 + lane;
            const int ol = task >> 2, pc = task & 3;
            uint4 pk = *(const uint4*)(stg + ol*40 + pc*8);
            const int o = pass*64 + ol, co = o >> 3, no = o & 7;
            *(uint4*)(g_votes + ((size_t)b << 21) + co*65536 + ci*2048 + no*256 + wrow + pc*8) = pk;
        }
        // iteration-1 logits fold (exact ints)
        #pragma unroll
        for (int i = 0; i < 8; i++) {
            const int task = i*32 + lane;
            const int pl = task >> 3, coi = task & 7;
            const int* a1 = a1s + pass*64 + coi*8;
            int dsum = 0;
            #pragma unroll
            for (int no = 0; no < 8; no++)
                dsum += a1[no] * (int)stg[(coi*8 + no)*40 + pl];
            g_logits[((b*32 + ci)*32 + pass*8 + coi)*256 + wrow + pl] =
                rintf((float)dsum * 0.00390625f) * 0.00390625f;
        }
        __syncwarp();
    }
}

// ---------------------------------------------------------------------------
// Kernel 2: softmax stats per (b, ci) over 8192 logits
// ---------------------------------------------------------------------------
__global__ void __launch_bounds__(256) softmax_kernel()
{
    const int row = blockIdx.x;
    const float* lp = g_logits + row*8192;
    const int t = threadIdx.x;
    float fl[32];
    #pragma unroll
    for (int i = 0; i < 32; i++) fl[i] = lp[i*256 + t];
    float m = fl[0];
    #pragma unroll
    for (int i = 1; i < 32; i++) m = fmaxf(m, fl[i]);
    __shared__ float red[8];
    #pragma unroll
    for (int off = 16; off; off >>= 1) m = fmaxf(m, __shfl_xor_sync(0xffffffffu, m, off));
    if ((t & 31) == 0) red[t >> 5] = m;
    __syncthreads();
    float M = red[0];
    #pragma unroll
    for (int i = 1; i < 8; i++) M = fmaxf(M, red[i]);
    __syncthreads();
    float s = 0.f;
    #pragma unroll
    for (int i = 0; i < 32; i++) s += expf(fl[i] - M);
    #pragma unroll
    for (int off = 16; off; off >>= 1) s += __shfl_xor_sync(0xffffffffu, s, off);
    if ((t & 31) == 0) red[t >> 5] = s;
    __syncthreads();
    if (t == 0) {
        float S = red[0];
        for (int i = 1; i < 8; i++) S += red[i];
        g_smax[row] = M;
        g_ssum[row] = S;
    }
}

// ---------------------------------------------------------------------------
// Kernel 3: fused routing iteration. block = (b, co, p-half); 128 threads.
// ---------------------------------------------------------------------------
__global__ void __launch_bounds__(128) route_kernel(
    const float* __restrict__ bias, float* __restrict__ out, int last)
{
    extern __shared__ char shb[];
    short* sv    = (short*)shb;                 // [32ci][8no][128p] = 65536 B
    float* smaxs = (float*)(shb + 65536);
    float* ssums = (float*)(shb + 65664);
    float* sb    = (float*)(shb + 65792);

    const int t   = threadIdx.x;
    const int blk = blockIdx.x;
    const int bco = blk >> 1, ph = blk & 1;
    const int b   = bco >> 5, co = bco & 31;

    {
        const short* src0 = g_votes + (size_t)bco*65536 + ph*128;
        uint4* dst = (uint4*)sv;
        #pragma unroll
        for (int r = 0; r < 32; r++) {
            int idx = r*128 + t;
            int cino = idx >> 4, ch = idx & 15;
            dst[idx] = *(const uint4*)(src0 + cino*256 + ch*8);
        }
    }
    if (t < 32) { smaxs[t] = g_smax[b*32 + t]; ssums[t] = g_ssum[b*32 + t]; }
    if (t < 8)  sb[t] = bias[co*8 + t];
    __syncthreads();

    float l[32];
    int S[8] = {0,0,0,0,0,0,0,0};
    const float* lgp = g_logits + (b*32)*8192 + co*256 + ph*128 + t;
    #pragma unroll
    for (int c = 0; c < 32; c++) {
        float lv = lgp[c*8192];
        l[c] = lv;
        float e = expf(lv - smaxs[c]);
        int r = __float2int_rn(__fmul_rn(__fdiv_rn(e, ssums[c]), 256.f));
        if (r) {
            #pragma unroll
            for (int no = 0; no < 8; no++)
                S[no] += r * (int)sv[(c*8 + no)*128 + t];
        }
    }
    float pq[8]; float ss = 0.f;
    #pragma unroll
    for (int no = 0; no < 8; no++) {
        float pre = __fadd_rn(__fmul_rn((float)S[no], 1.52587890625e-05f), sb[no]);
        float q = rintf(__fmul_rn(pre, 256.f)) * 0.00390625f;
        pq[no] = q; ss = __fadd_rn(ss, __fmul_rn(q, q));
    }
    float n   = sqrtf(ss);
    float den = __fadd_rn(1.f, __fmul_rn(n, n));
    int ai[8];
    #pragma unroll
    for (int no = 0; no < 8; no++) {
        float a = __fdiv_rn(__fmul_rn(pq[no], n), den);
        int q = __float2int_rn(__fmul_rn(a, 256.f));
        ai[no] = q;
        out[(bco*8 + no)*256 + ph*128 + t] = (float)q * 0.00390625f;
    }
    if (!last) {
        float* lw = g_logits + (b*32)*8192 + co*256 + ph*128 + t;
        #pragma unroll
        for (int c = 0; c < 32; c++) {
            int m = 0;
            #pragma unroll
            for (int no = 0; no < 8; no++)
                m += ai[no] * (int)sv[(c*8 + no)*128 + t];
            float lg = __fadd_rn(l[c], __fmul_rn((float)m, 1.52587890625e-05f));
            lw[c*8192] = rintf(__fmul_rn(lg, 256.f)) * 0.00390625f;
        }
    }
}

// ---------------------------------------------------------------------------
extern "C" void kernel_launch(void* const* d_in, const int* in_sizes, int n_in,
                              void* d_out, int out_size)
{
    const float* x    = (const float*)d_in[0];
    const float* w    = (const float*)d_in[1];
    const float* cb   = (const float*)d_in[2];
    const float* bias = (const float*)d_in[3];
    float* out = (float*)d_out;
    (void)in_sizes; (void)n_in; (void)out_size;

    const int ROUTE_SMEM = 65824;
    cudaFuncSetAttribute(conv_votes_kernel, cudaFuncAttributeMaxDynamicSharedMemorySize, CONV_SMEM);
    cudaFuncSetAttribute(route_kernel,      cudaFuncAttributeMaxDynamicSharedMemorySize, ROUTE_SMEM);

    conv_votes_kernel<<<1024, 256, CONV_SMEM>>>(x, w, cb, bias);  // + iteration 1 folded
    softmax_kernel<<<1024, 256>>>();                              // iteration 2
    route_kernel<<<2048, 128, ROUTE_SMEM>>>(bias, out, 0);
    softmax_kernel<<<1024, 256>>>();                              // iteration 3
    route_kernel<<<2048, 128, ROUTE_SMEM>>>(bias, out, 1);
}

// round 7
// speedup vs baseline: 1.0207x; 1.0207x over previous
#include <cuda_runtime.h>
#include <cuda_fp16.h>
#include <cstdint>

#define BSZ 32
#define CIc 32
#define PP  256

__device__ short g_votes[BSZ*32*CIc*8*PP];   // [b][co][ci][no][p], value*256 (exact)
__device__ float g_logits[BSZ*CIc*32*PP];    // [b][ci][co][p]
__device__ float g_smax[BSZ*CIc];
__device__ float g_ssum[BSZ*CIc];

// ---------------- helpers ----------------
static __device__ __forceinline__ uint32_t smem_u32(const void* p) {
    uint32_t a;
    asm("{ .reg .u64 t; cvta.to.shared.u64 t, %1; cvt.u32.u64 %0, t; }" : "=r"(a) : "l"(p));
    return a;
}

#define MMA16816(d, a, b) \
    asm volatile("mma.sync.aligned.m16n8k16.row.col.f32.f16.f16.f32 " \
        "{%0,%1,%2,%3}, {%4,%5,%6,%7}, {%8,%9}, {%0,%1,%2,%3};" \
        : "+f"((d)[0]), "+f"((d)[1]), "+f"((d)[2]), "+f"((d)[3]) \
        : "r"((a)[0]), "r"((a)[1]), "r"((a)[2]), "r"((a)[3]), "r"((b)[0]), "r"((b)[1]))

#define LDMX4(r0, r1, r2, r3, addr) \
    asm volatile("ldmatrix.sync.aligned.m8n8.x4.shared.b16 {%0,%1,%2,%3}, [%4];" \
        : "=r"(r0), "=r"(r1), "=r"(r2), "=r"(r3) : "r"(addr))

static __device__ __forceinline__ uint32_t packh(__half a, __half b) {
    return (uint32_t)__half_as_ushort(a) | ((uint32_t)__half_as_ushort(b) << 16);
}
// rn fp16 2-term split of a float pair; returns hi pair, writes lo pair.
static __device__ __forceinline__ uint32_t packsplit(float f0, float f1, uint32_t &lo) {
    __half h0 = __float2half_rn(f0), h1 = __float2half_rn(f1);
    __half l0 = __float2half_rn(__fsub_rn(f0, __half2float(h0)));
    __half l1 = __float2half_rn(__fsub_rn(f1, __half2float(h1)));
    lo = packh(l0, l1);
    return packh(h0, h1);
}

// smem layout: 176B rows (72 real fp16 k + pad). 44i mod 32 covers all banks ->
// ldmatrix conflict-free (the 160B stride in R6 was a 4-way conflict: 40i mod 32).
#define ROWB       176u
#define BHI_OFF    0u                        // [256 o][176B]
#define BLO_OFF    45056u
#define AHI_OFF    90112u                    // [256 p][176B]
#define ALO_OFF    135168u
#define STG_OFF    180224u                   // 8 warps * 64o*40p shorts = 40960 (x tile aliased)
#define CBS_OFF    221184u
#define A1S_OFF    222208u
#define KLUT_OFF   223232u
#define CONV_SMEM  223616

// ---------------------------------------------------------------------------
// Kernel 1: fp16-split mma.sync conv -> int16 votes + iteration-1 logits.
// block = (b, ci): D[256p, 256o] = X[256,72] * W^T, K padded to 80.
// A and B in smem as fp16 hi/lo; ldmatrix fragments; 3 products hh+hl+lh.
// ---------------------------------------------------------------------------
__global__ void __launch_bounds__(256, 1) conv_votes_kernel(
    const float* __restrict__ x, const float* __restrict__ w,
    const float* __restrict__ cb, const float* __restrict__ bias)
{
    extern __shared__ char sh[];
    float* xs  = (float*)(sh + STG_OFF);    // aliased: x pad tile, dead before staging
    float* cbs = (float*)(sh + CBS_OFF);
    int*   a1s = (int*)(sh + A1S_OFF);
    int*   klut= (int*)(sh + KLUT_OFF);
    const uint32_t smb = smem_u32(sh);

    const int t = threadIdx.x;
    const int wid = t >> 5, lane = t & 31;
    const int b = blockIdx.x >> 5, ci = blockIdx.x & 31;

    // --- fills ---
    for (int i = t; i < 2592; i += 256) xs[i] = 0.f;
    cbs[t] = cb[t];
    if (t < 72) { int ni = t/9, r = t%9; klut[t] = ni*324 + (r/3)*18 + (r%3); }
    if (t < 32) {   // iteration-1 activation from bias (quant(route)==0)
        float pv[8]; float ss = 0.f;
        #pragma unroll
        for (int no = 0; no < 8; no++) {
            float q = rintf(__fmul_rn(bias[t*8+no], 256.f)) * 0.00390625f;
            pv[no] = q; ss = __fadd_rn(ss, __fmul_rn(q, q));
        }
        float n = sqrtf(ss);
        float den = __fadd_rn(1.f, __fmul_rn(n, n));
        #pragma unroll
        for (int no = 0; no < 8; no++) {
            float a = __fdiv_rn(__fmul_rn(pv[no], n), den);
            a1s[t*8+no] = __float2int_rn(__fmul_rn(a, 256.f));
        }
    }
    // B fill: this thread's o = t; W row -> hi/lo fp16, 176B rows
    {
        const float4* wr = (const float4*)(w + t*72);
        char* bh = sh + BHI_OFF + t*ROWB;
        char* bl = sh + BLO_OFF + t*ROWB;
        #pragma unroll
        for (int q = 0; q < 18; q++) {
            float4 v = wr[q];
            uint32_t l0, l1;
            uint32_t h0 = packsplit(v.x, v.y, l0);
            uint32_t h1 = packsplit(v.z, v.w, l1);
            *(uint2*)(bh + q*8) = make_uint2(h0, h1);
            *(uint2*)(bl + q*8) = make_uint2(l0, l1);
        }
        *(uint4*)(bh + 144) = make_uint4(0,0,0,0);   // k pad 72..79 (ldmatrix reads <160)
        *(uint4*)(bl + 144) = make_uint4(0,0,0,0);
    }
    __syncthreads();
    {   // x interior (zeros already placed for halo)
        const float* xb = x + (b*CIc + ci)*8*PP;
        #pragma unroll
        for (int i = 0; i < 8; i++) {
            int idx = t + i*256;
            int ni = idx >> 8, rem = idx & 255;
            xs[ni*324 + ((rem>>4)+1)*18 + (rem&15) + 1] = xb[idx];
        }
    }
    __syncthreads();
    // A fill: this thread's p = t; im2col row -> hi/lo fp16, 176B rows
    {
        const int xyb = (t >> 4)*18 + (t & 15);
        char* ah = sh + AHI_OFF + t*ROWB;
        char* al = sh + ALO_OFF + t*ROWB;
        #pragma unroll
        for (int q = 0; q < 9; q++) {       // 9*8 = 72 real k
            uint32_t h[4], l[4];
            #pragma unroll
            for (int j = 0; j < 4; j++) {
                int k0 = q*8 + 2*j;
                float f0 = xs[klut[k0]   + xyb];
                float f1 = xs[klut[k0+1] + xyb];
                h[j] = packsplit(f0, f1, l[j]);
            }
            *(uint4*)(ah + q*16) = make_uint4(h[0], h[1], h[2], h[3]);
            *(uint4*)(al + q*16) = make_uint4(l[0], l[1], l[2], l[3]);
        }
        *(uint4*)(ah + 144) = make_uint4(0,0,0,0);
        *(uint4*)(al + 144) = make_uint4(0,0,0,0);
    }
    __syncthreads();   // xs (stage alias) dead from here

    const int wrow = wid*32;
    const int lane2 = (lane & 3)*2;
    short* stg = (short*)(sh + STG_OFF) + wid*2560;   // [64 o][40 p-pad] shorts

    #pragma unroll 1
    for (int pass = 0; pass < 4; pass++) {
        float acc[2][8][4];
        #pragma unroll
        for (int mt = 0; mt < 2; mt++)
            #pragma unroll
            for (int nt = 0; nt < 8; nt++)
                #pragma unroll
                for (int j = 0; j < 4; j++) acc[mt][nt][j] = 0.f;

        #pragma unroll
        for (int kc = 0; kc < 5; kc++) {
            // A fragments via ldmatrix (row-major [p][k])
            uint32_t ah[2][4], al2[2][4];
            #pragma unroll
            for (int mt = 0; mt < 2; mt++) {
                const uint32_t arow = wrow + mt*16 + (lane & 15);
                const uint32_t aoff = arow*ROWB + kc*32 + ((lane >> 4) << 4);
                LDMX4(ah[mt][0], ah[mt][1], ah[mt][2], ah[mt][3], smb + AHI_OFF + aoff);
                LDMX4(al2[mt][0], al2[mt][1], al2[mt][2], al2[mt][3], smb + ALO_OFF + aoff);
            }
            // B fragments via ldmatrix ([o][k] rows)
            uint32_t bh[8][2], bl[8][2];
            #pragma unroll
            for (int g = 0; g < 4; g++) {
                const uint32_t row = pass*64 + g*16 + (lane & 7) + ((lane >> 4) << 3);
                const uint32_t koff = kc*32 + ((lane >> 3) & 1)*16;
                LDMX4(bh[2*g][0], bh[2*g][1], bh[2*g+1][0], bh[2*g+1][1],
                      smb + BHI_OFF + row*ROWB + koff);
                LDMX4(bl[2*g][0], bl[2*g][1], bl[2*g+1][0], bl[2*g+1][1],
                      smb + BLO_OFF + row*ROWB + koff);
            }
            #pragma unroll
            for (int mt = 0; mt < 2; mt++)
                #pragma unroll
                for (int nt = 0; nt < 8; nt++) {
                    MMA16816(acc[mt][nt], ah[mt], bh[nt]);
                    MMA16816(acc[mt][nt], ah[mt], bl[nt]);
                    MMA16816(acc[mt][nt], al2[mt], bh[nt]);
                }
        }

        // --- epilogue: quantize, stage transposed [o][p], then wide stores ---
        #pragma unroll
        for (int mt = 0; mt < 2; mt++) {
            const int r = (lane >> 2) + mt*16;
            #pragma unroll
            for (int nt = 0; nt < 8; nt++) {
                const int c = nt*8 + lane2;
                const int o0 = pass*64 + c;
                int v0 = __float2int_rn((acc[mt][nt][0] + cbs[o0])   * 256.f);
                int v1 = __float2int_rn((acc[mt][nt][1] + cbs[o0+1]) * 256.f);
                int v2 = __float2int_rn((acc[mt][nt][2] + cbs[o0])   * 256.f);
                int v3 = __float2int_rn((acc[mt][nt][3] + cbs[o0+1]) * 256.f);
                stg[c*40 + r]         = (short)v0;
                stg[(c+1)*40 + r]     = (short)v1;
                stg[c*40 + r + 8]     = (short)v2;
                stg[(c+1)*40 + r + 8] = (short)v3;
            }
        }
        __syncwarp();

        // votes out: uint4 = 8 consecutive p
        #pragma unroll
        for (int i = 0; i < 8; i++) {
            const int task = i*32 + lane;
            const int ol = task >> 2, pc = task & 3;
            uint4 pk = *(const uint4*)(stg + ol*40 + pc*8);
            const int o = pass*64 + ol, co = o >> 3, no = o & 7;
            *(uint4*)(g_votes + ((size_t)b << 21) + co*65536 + ci*2048 + no*256 + wrow + pc*8) = pk;
        }
        // iteration-1 logits fold (exact ints)
        #pragma unroll
        for (int i = 0; i < 8; i++) {
            const int task = i*32 + lane;
            const int pl = task >> 3, coi = task & 7;
            const int* a1 = a1s + pass*64 + coi*8;
            int dsum = 0;
            #pragma unroll
            for (int no = 0; no < 8; no++)
                dsum += a1[no] * (int)stg[(coi*8 + no)*40 + pl];
            g_logits[((b*32 + ci)*32 + pass*8 + coi)*256 + wrow + pl] =
                rintf((float)dsum * 0.00390625f) * 0.00390625f;
        }
        __syncwarp();
    }
}

// ---------------------------------------------------------------------------
// Kernel 2: softmax stats per (b, ci) over 8192 logits
// ---------------------------------------------------------------------------
__global__ void __launch_bounds__(256) softmax_kernel()
{
    const int row = blockIdx.x;
    const float* lp = g_logits + row*8192;
    const int t = threadIdx.x;
    float fl[32];
    #pragma unroll
    for (int i = 0; i < 32; i++) fl[i] = lp[i*256 + t];
    float m = fl[0];
    #pragma unroll
    for (int i = 1; i < 32; i++) m = fmaxf(m, fl[i]);
    __shared__ float red[8];
    #pragma unroll
    for (int off = 16; off; off >>= 1) m = fmaxf(m, __shfl_xor_sync(0xffffffffu, m, off));
    if ((t & 31) == 0) red[t >> 5] = m;
    __syncthreads();
    float M = red[0];
    #pragma unroll
    for (int i = 1; i < 8; i++) M = fmaxf(M, red[i]);
    __syncthreads();
    float s = 0.f;
    #pragma unroll
    for (int i = 0; i < 32; i++) s += expf(fl[i] - M);
    #pragma unroll
    for (int off = 16; off; off >>= 1) s += __shfl_xor_sync(0xffffffffu, s, off);
    if ((t & 31) == 0) red[t >> 5] = s;
    __syncthreads();
    if (t == 0) {
        float S = red[0];
        for (int i = 1; i < 8; i++) S += red[i];
        g_smax[row] = M;
        g_ssum[row] = S;
    }
}

// ---------------------------------------------------------------------------
// Kernel 3: fused routing iteration. block = (b, co, p-half); 128 threads.
// ---------------------------------------------------------------------------
__global__ void __launch_bounds__(128) route_kernel(
    const float* __restrict__ bias, float* __restrict__ out, int last)
{
    extern __shared__ char shb[];
    short* sv    = (short*)shb;                 // [32ci][8no][128p] = 65536 B
    float* smaxs = (float*)(shb + 65536);
    float* ssums = (float*)(shb + 65664);
    float* sb    = (float*)(shb + 65792);

    const int t   = threadIdx.x;
    const int blk = blockIdx.x;
    const int bco = blk >> 1, ph = blk & 1;
    const int b   = bco >> 5, co = bco & 31;

    {
        const short* src0 = g_votes + (size_t)bco*65536 + ph*128;
        uint4* dst = (uint4*)sv;
        #pragma unroll
        for (int r = 0; r < 32; r++) {
            int idx = r*128 + t;
            int cino = idx >> 4, ch = idx & 15;
            dst[idx] = *(const uint4*)(src0 + cino*256 + ch*8);
        }
    }
    if (t < 32) { smaxs[t] = g_smax[b*32 + t]; ssums[t] = g_ssum[b*32 + t]; }
    if (t < 8)  sb[t] = bias[co*8 + t];
    __syncthreads();

    float l[32];
    int S[8] = {0,0,0,0,0,0,0,0};
    const float* lgp = g_logits + (b*32)*8192 + co*256 + ph*128 + t;
    #pragma unroll
    for (int c = 0; c < 32; c++) {
        float lv = lgp[c*8192];
        l[c] = lv;
        float e = expf(lv - smaxs[c]);
        int r = __float2int_rn(__fmul_rn(__fdiv_rn(e, ssums[c]), 256.f));
        if (r) {
            #pragma unroll
            for (int no = 0; no < 8; no++)
                S[no] += r * (int)sv[(c*8 + no)*128 + t];
        }
    }
    float pq[8]; float ss = 0.f;
    #pragma unroll
    for (int no = 0; no < 8; no++) {
        float pre = __fadd_rn(__fmul_rn((float)S[no], 1.52587890625e-05f), sb[no]);
        float q = rintf(__fmul_rn(pre, 256.f)) * 0.00390625f;
        pq[no] = q; ss = __fadd_rn(ss, __fmul_rn(q, q));
    }
    float n   = sqrtf(ss);
    float den = __fadd_rn(1.f, __fmul_rn(n, n));
    int ai[8];
    #pragma unroll
    for (int no = 0; no < 8; no++) {
        float a = __fdiv_rn(__fmul_rn(pq[no], n), den);
        int q = __float2int_rn(__fmul_rn(a, 256.f));
        ai[no] = q;
        out[(bco*8 + no)*256 + ph*128 + t] = (float)q * 0.00390625f;
    }
    if (!last) {
        float* lw = g_logits + (b*32)*8192 + co*256 + ph*128 + t;
        #pragma unroll
        for (int c = 0; c < 32; c++) {
            int m = 0;
            #pragma unroll
            for (int no = 0; no < 8; no++)
                m += ai[no] * (int)sv[(c*8 + no)*128 + t];
            float lg = __fadd_rn(l[c], __fmul_rn((float)m, 1.52587890625e-05f));
            lw[c*8192] = rintf(__fmul_rn(lg, 256.f)) * 0.00390625f;
        }
    }
}

// ---------------------------------------------------------------------------
extern "C" void kernel_launch(void* const* d_in, const int* in_sizes, int n_in,
                              void* d_out, int out_size)
{
    const float* x    = (const float*)d_in[0];
    const float* w    = (const float*)d_in[1];
    const float* cb   = (const float*)d_in[2];
    const float* bias = (const float*)d_in[3];
    float* out = (float*)d_out;
    (void)in_sizes; (void)n_in; (void)out_size;

    const int ROUTE_SMEM = 65824;
    cudaFuncSetAttribute(conv_votes_kernel, cudaFuncAttributeMaxDynamicSharedMemorySize, CONV_SMEM);
    cudaFuncSetAttribute(route_kernel,      cudaFuncAttributeMaxDynamicSharedMemorySize, ROUTE_SMEM);

    conv_votes_kernel<<<1024, 256, CONV_SMEM>>>(x, w, cb, bias);  // + iteration 1 folded
    softmax_kernel<<<1024, 256>>>();                              // iteration 2
    route_kernel<<<2048, 128, ROUTE_SMEM>>>(bias, out, 0);
    softmax_kernel<<<1024, 256>>>();                              // iteration 3
    route_kernel<<<2048, 128, ROUTE_SMEM>>>(bias, out, 1);
}

// round 8
// speedup vs baseline: 1.1727x; 1.1489x over previous
#include <cuda_runtime.h>
#include <cuda_fp16.h>
#include <cstdint>

#define BSZ 32
#define CIc 32
#define PP  256

__device__ short g_votes[BSZ*32*CIc*8*PP];   // [b][co][ci][no][p], value*256 (exact)
__device__ float g_logits[BSZ*CIc*32*PP];    // [b][ci][co][p]
__device__ float g_smax[BSZ*CIc];
__device__ float g_ssum[BSZ*CIc];
__device__ uint4  g_wsplit[5632];            // W fp16 hi[0..45056) lo[45056..90112), 176B rows
__device__ __half g_xh[BSZ*CIc*2048];        // x fp16 hi, [b][ci][ni][16][16]
__device__ __half g_xl[BSZ*CIc*2048];        // x fp16 lo

// ---------------- helpers ----------------
static __device__ __forceinline__ uint32_t smem_u32(const void* p) {
    uint32_t a;
    asm("{ .reg .u64 t; cvta.to.shared.u64 t, %1; cvt.u32.u64 %0, t; }" : "=r"(a) : "l"(p));
    return a;
}

#define MMA16816(d, a, b) \
    asm volatile("mma.sync.aligned.m16n8k16.row.col.f32.f16.f16.f32 " \
        "{%0,%1,%2,%3}, {%4,%5,%6,%7}, {%8,%9}, {%0,%1,%2,%3};" \
        : "+f"((d)[0]), "+f"((d)[1]), "+f"((d)[2]), "+f"((d)[3]) \
        : "r"((a)[0]), "r"((a)[1]), "r"((a)[2]), "r"((a)[3]), "r"((b)[0]), "r"((b)[1]))

#define MMA1688(d, a0, a1, b0) \
    asm volatile("mma.sync.aligned.m16n8k8.row.col.f32.f16.f16.f32 " \
        "{%0,%1,%2,%3}, {%4,%5}, {%6}, {%0,%1,%2,%3};" \
        : "+f"((d)[0]), "+f"((d)[1]), "+f"((d)[2]), "+f"((d)[3]) \
        : "r"(a0), "r"(a1), "r"(b0))

#define LDMX4(r0, r1, r2, r3, addr) \
    asm volatile("ldmatrix.sync.aligned.m8n8.x4.shared.b16 {%0,%1,%2,%3}, [%4];" \
        : "=r"(r0), "=r"(r1), "=r"(r2), "=r"(r3) : "r"(addr))

static __device__ __forceinline__ uint32_t packh(__half a, __half b) {
    return (uint32_t)__half_as_ushort(a) | ((uint32_t)__half_as_ushort(b) << 16);
}
// rn fp16 2-term split of a float pair; returns hi pair, writes lo pair.
static __device__ __forceinline__ uint32_t packsplit(float f0, float f1, uint32_t &lo) {
    __half h0 = __float2half_rn(f0), h1 = __float2half_rn(f1);
    __half l0 = __float2half_rn(__fsub_rn(f0, __half2float(h0)));
    __half l1 = __float2half_rn(__fsub_rn(f1, __half2float(h1)));
    lo = packh(l0, l1);
    return packh(h0, h1);
}

// 176B rows: 44*i mod 32 covers all banks -> ldmatrix conflict-free
#define ROWB       176u
#define BHI_OFF    0u                       // [256 o][176B]
#define BLO_OFF    45056u
#define AHI_OFF    90112u                   // [256 p][176B]
#define ALO_OFF    135168u
#define XSH_OFF    180224u                  // padded x tile halves [8][18][18]
#define XSL_OFF    185408u
#define CBS_OFF    190592u                  // 256 floats
#define A1S_OFF    191616u                  // 256 ints
#define KLUT_OFF   192640u                  // 72 ints
#define CONV_SMEM  192928

// ---------------------------------------------------------------------------
// Prep 1: W -> fp16 hi/lo in final ldmatrix row layout (one block, once)
// ---------------------------------------------------------------------------
__global__ void __launch_bounds__(256) prep_w_kernel(const float* __restrict__ w)
{
    const int o = threadIdx.x;
    const float4* wr = (const float4*)(w + o*72);
    char* bh = (char*)g_wsplit + o*ROWB;
    char* bl = (char*)g_wsplit + 45056 + o*ROWB;
    #pragma unroll
    for (int q = 0; q < 18; q++) {
        float4 v = wr[q];
        uint32_t l0, l1;
        uint32_t h0 = packsplit(v.x, v.y, l0);
        uint32_t h1 = packsplit(v.z, v.w, l1);
        *(uint2*)(bh + q*8) = make_uint2(h0, h1);
        *(uint2*)(bl + q*8) = make_uint2(l0, l1);
    }
    *(uint4*)(bh + 144) = make_uint4(0,0,0,0);
    *(uint4*)(bh + 160) = make_uint4(0,0,0,0);
    *(uint4*)(bl + 144) = make_uint4(0,0,0,0);
    *(uint4*)(bl + 160) = make_uint4(0,0,0,0);
}

// ---------------------------------------------------------------------------
// Prep 2: x -> fp16 hi/lo (per-element split, before im2col)
// ---------------------------------------------------------------------------
__global__ void __launch_bounds__(256) prep_x_kernel(const float* __restrict__ x)
{
    const int tile = blockIdx.x;           // b*32 + ci
    const float4* src = (const float4*)(x + tile*2048);
    #pragma unroll
    for (int i = 0; i < 2; i++) {
        int idx4 = threadIdx.x + i*256;
        float4 v = src[idx4];
        uint32_t l0, l1;
        uint32_t h0 = packsplit(v.x, v.y, l0);
        uint32_t h1 = packsplit(v.z, v.w, l1);
        *(uint2*)(g_xh + tile*2048 + idx4*4) = make_uint2(h0, h1);
        *(uint2*)(g_xl + tile*2048 + idx4*4) = make_uint2(l0, l1);
    }
}

// ---------------------------------------------------------------------------
// Kernel 1: fp16-split mma.sync conv -> int16 votes + iteration-1 logits.
// block = (b, ci), 512 threads / 16 warps. Warp tile 32p x 32o, 4 passes.
// K = 72 exact: 4 x k16 + 1 x k8. 3 products hh+hl+lh (exact in vote quantum).
// ---------------------------------------------------------------------------
__global__ void __launch_bounds__(512, 1) conv_votes_kernel(
    const float* __restrict__ cb, const float* __restrict__ bias)
{
    extern __shared__ char sh[];
    float* cbs = (float*)(sh + CBS_OFF);
    int*   a1s = (int*)(sh + A1S_OFF);
    int*   klut= (int*)(sh + KLUT_OFF);
    const uint32_t smb = smem_u32(sh);

    const int t = threadIdx.x;
    const int wid = t >> 5, lane = t & 31;
    const int b = blockIdx.x >> 5, ci = blockIdx.x & 31;

    // --- phase 0: B copy (pure memcpy), zero x pads, constants ---
    {
        const uint4* src = g_wsplit;
        uint4* dst = (uint4*)sh;           // BHI/BLO contiguous [0, 90112)
        #pragma unroll
        for (int i = 0; i < 11; i++) dst[t + i*512] = src[t + i*512];
    }
    {   // zero both padded x tiles (2592 uints total across the two arrays)
        uint32_t* z = (uint32_t*)(sh + XSH_OFF);
        #pragma unroll
        for (int i = 0; i < 6; i++) {
            int idx = t + i*512;
            if (idx < 2592) z[idx] = 0;
        }
    }
    if (t < 256) cbs[t] = cb[t];
    if (t < 72) { int ni = t/9, r = t%9; klut[t] = ni*324 + (r/3)*18 + (r%3); }
    if (t < 32) {   // iteration-1 activation from bias (quant(route)==0)
        float pv[8]; float ss = 0.f;
        #pragma unroll
        for (int no = 0; no < 8; no++) {
            float q = rintf(__fmul_rn(bias[t*8+no], 256.f)) * 0.00390625f;
            pv[no] = q; ss = __fadd_rn(ss, __fmul_rn(q, q));
        }
        float n = sqrtf(ss);
        float den = __fadd_rn(1.f, __fmul_rn(n, n));
        #pragma unroll
        for (int no = 0; no < 8; no++) {
            float a = __fdiv_rn(__fmul_rn(pv[no], n), den);
            a1s[t*8+no] = __float2int_rn(__fmul_rn(a, 256.f));
        }
    }
    __syncthreads();

    // --- phase 1: x tile interior (pre-split halves, pure gathers) ---
    {
        const __half* xh = g_xh + blockIdx.x*2048;
        const __half* xl = g_xl + blockIdx.x*2048;
        unsigned short* dh = (unsigned short*)(sh + XSH_OFF);
        unsigned short* dl = (unsigned short*)(sh + XSL_OFF);
        #pragma unroll
        for (int i = 0; i < 4; i++) {
            int idx = t + i*512;
            int ni = idx >> 8, rem = idx & 255;
            int dsto = ni*324 + ((rem>>4)+1)*18 + (rem&15) + 1;
            dh[dsto] = __half_as_ushort(xh[idx]);
            dl[dsto] = __half_as_ushort(xl[idx]);
        }
    }
    __syncthreads();

    // --- phase 2: A build (im2col gather of pre-split halves) ---
    {
        const int p = t & 255;
        const unsigned short* xsrc = (unsigned short*)(sh + ((t < 256) ? XSH_OFF : XSL_OFF));
        char* dst = sh + ((t < 256) ? AHI_OFF : ALO_OFF) + p*ROWB;
        const int xyb = (p >> 4)*18 + (p & 15);
        #pragma unroll
        for (int q = 0; q < 9; q++) {
            uint32_t u[4];
            #pragma unroll
            for (int j = 0; j < 4; j++) {
                uint32_t v0 = xsrc[klut[q*8 + 2*j]     + xyb];
                uint32_t v1 = xsrc[klut[q*8 + 2*j + 1] + xyb];
                u[j] = v0 | (v1 << 16);
            }
            *(uint4*)(dst + q*16) = make_uint4(u[0], u[1], u[2], u[3]);
        }
        *(uint4*)(dst + 144) = make_uint4(0,0,0,0);
        *(uint4*)(dst + 160) = make_uint4(0,0,0,0);
    }
    __syncthreads();

    // --- MMA: warp w -> p-base (w&7)*32, o-quarter (w>>3)*128, 4 o-passes ---
    const int pbase = (wid & 7)*32;
    const int obase = (wid >> 3)*128;
    const int lane2 = (lane & 3)*2;

    #pragma unroll 1
    for (int pass = 0; pass < 4; pass++) {
        const int otile = obase + pass*32;
        float acc[2][4][4];
        #pragma unroll
        for (int mt = 0; mt < 2; mt++)
            #pragma unroll
            for (int nt = 0; nt < 4; nt++)
                #pragma unroll
                for (int j = 0; j < 4; j++) acc[mt][nt][j] = 0.f;

        #pragma unroll
        for (int kc = 0; kc < 5; kc++) {
            // A fragments (row-major [p][k])
            uint32_t ah[2][4], al[2][4];
            #pragma unroll
            for (int mt = 0; mt < 2; mt++) {
                const uint32_t arow = pbase + mt*16 + (lane & 15);
                const uint32_t aoff = arow*ROWB + kc*32 + ((lane >> 4) << 4);
                LDMX4(ah[mt][0], ah[mt][1], ah[mt][2], ah[mt][3], smb + AHI_OFF + aoff);
                LDMX4(al[mt][0], al[mt][1], al[mt][2], al[mt][3], smb + ALO_OFF + aoff);
            }
            // B fragments ([o][k] rows) — R7-proven addressing
            uint32_t bh[4][2], bl[4][2];
            #pragma unroll
            for (int g = 0; g < 2; g++) {
                const uint32_t row = otile + g*16 + (lane & 7) + ((lane >> 4) << 3);
                const uint32_t koff = kc*32 + ((lane >> 3) & 1)*16;
                LDMX4(bh[2*g][0], bh[2*g][1], bh[2*g+1][0], bh[2*g+1][1],
                      smb + BHI_OFF + row*ROWB + koff);
                LDMX4(bl[2*g][0], bl[2*g][1], bl[2*g+1][0], bl[2*g+1][1],
                      smb + BLO_OFF + row*ROWB + koff);
            }
            if (kc < 4) {
                #pragma unroll
                for (int mt = 0; mt < 2; mt++)
                    #pragma unroll
                    for (int nt = 0; nt < 4; nt++) {
                        MMA16816(acc[mt][nt], ah[mt], bh[nt]);
                        MMA16816(acc[mt][nt], ah[mt], bl[nt]);
                        MMA16816(acc[mt][nt], al[mt], bh[nt]);
                    }
            } else {   // k 64..71 only: m16n8k8 (pad products would be exact zeros)
                #pragma unroll
                for (int mt = 0; mt < 2; mt++)
                    #pragma unroll
                    for (int nt = 0; nt < 4; nt++) {
                        MMA1688(acc[mt][nt], ah[mt][0], ah[mt][1], bh[nt][0]);
                        MMA1688(acc[mt][nt], ah[mt][0], ah[mt][1], bl[nt][0]);
                        MMA1688(acc[mt][nt], al[mt][0], al[mt][1], bh[nt][0]);
                    }
            }
        }

        // --- epilogue: quant votes direct-to-global + quad-shuffle logit fold ---
        #pragma unroll
        for (int mt = 0; mt < 2; mt++) {
            const int p0 = pbase + mt*16 + (lane >> 2);
            #pragma unroll
            for (int nt = 0; nt < 4; nt++) {
                const int o = otile + nt*8 + lane2;     // even: o, o+1 share co
                const float cb0 = cbs[o], cb1 = cbs[o+1];
                int v0 = __float2int_rn((acc[mt][nt][0] + cb0) * 256.f);
                int v1 = __float2int_rn((acc[mt][nt][1] + cb1) * 256.f);
                int v2 = __float2int_rn((acc[mt][nt][2] + cb0) * 256.f);
                int v3 = __float2int_rn((acc[mt][nt][3] + cb1) * 256.f);
                short* vb = g_votes + ((size_t)b << 21) + (o >> 3)*65536
                          + ci*2048 + (o & 7)*256;
                vb[p0]       = (short)v0;
                vb[256 + p0] = (short)v1;
                vb[p0 + 8]       = (short)v2;
                vb[256 + p0 + 8] = (short)v3;
                int s0 = a1s[o]*v0 + a1s[o+1]*v1;       // p0
                int s1 = a1s[o]*v2 + a1s[o+1]*v3;       // p0+8
                s0 += __shfl_xor_sync(0xffffffffu, s0, 1);
                s0 += __shfl_xor_sync(0xffffffffu, s0, 2);
                s1 += __shfl_xor_sync(0xffffffffu, s1, 1);
                s1 += __shfl_xor_sync(0xffffffffu, s1, 2);
                if ((lane & 3) == 0) {
                    const int co = o >> 3;
                    float* lb = g_logits + ((b*32 + ci)*32 + co)*256;
                    lb[p0]     = rintf((float)s0 * 0.00390625f) * 0.00390625f;
                    lb[p0 + 8] = rintf((float)s1 * 0.00390625f) * 0.00390625f;
                }
            }
        }
    }
}

// ---------------------------------------------------------------------------
// Kernel 2: softmax stats per (b, ci) over 8192 logits
// ---------------------------------------------------------------------------
__global__ void __launch_bounds__(256) softmax_kernel()
{
    const int row = blockIdx.x;
    const float* lp = g_logits + row*8192;
    const int t = threadIdx.x;
    float fl[32];
    #pragma unroll
    for (int i = 0; i < 32; i++) fl[i] = lp[i*256 + t];
    float m = fl[0];
    #pragma unroll
    for (int i = 1; i < 32; i++) m = fmaxf(m, fl[i]);
    __shared__ float red[8];
    #pragma unroll
    for (int off = 16; off; off >>= 1) m = fmaxf(m, __shfl_xor_sync(0xffffffffu, m, off));
    if ((t & 31) == 0) red[t >> 5] = m;
    __syncthreads();
    float M = red[0];
    #pragma unroll
    for (int i = 1; i < 8; i++) M = fmaxf(M, red[i]);
    __syncthreads();
    float s = 0.f;
    #pragma unroll
    for (int i = 0; i < 32; i++) s += expf(fl[i] - M);
    #pragma unroll
    for (int off = 16; off; off >>= 1) s += __shfl_xor_sync(0xffffffffu, s, off);
    if ((t & 31) == 0) red[t >> 5] = s;
    __syncthreads();
    if (t == 0) {
        float S = red[0];
        for (int i = 1; i < 8; i++) S += red[i];
        g_smax[row] = M;
        g_ssum[row] = S;
    }
}

// ---------------------------------------------------------------------------
// Kernel 3: fused routing iteration. block = (b, co, p-half); 128 threads.
// ---------------------------------------------------------------------------
__global__ void __launch_bounds__(128) route_kernel(
    const float* __restrict__ bias, float* __restrict__ out, int last)
{
    extern __shared__ char shb[];
    short* sv    = (short*)shb;                 // [32ci][8no][128p] = 65536 B
    float* smaxs = (float*)(shb + 65536);
    float* ssums = (float*)(shb + 65664);
    float* sb    = (float*)(shb + 65792);

    const int t   = threadIdx.x;
    const int blk = blockIdx.x;
    const int bco = blk >> 1, ph = blk & 1;
    const int b   = bco >> 5, co = bco & 31;

    {
        const short* src0 = g_votes + (size_t)bco*65536 + ph*128;
        uint4* dst = (uint4*)sv;
        #pragma unroll
        for (int r = 0; r < 32; r++) {
            int idx = r*128 + t;
            int cino = idx >> 4, ch = idx & 15;
            dst[idx] = *(const uint4*)(src0 + cino*256 + ch*8);
        }
    }
    if (t < 32) { smaxs[t] = g_smax[b*32 + t]; ssums[t] = g_ssum[b*32 + t]; }
    if (t < 8)  sb[t] = bias[co*8 + t];
    __syncthreads();

    float l[32];
    int S[8] = {0,0,0,0,0,0,0,0};
    const float* lgp = g_logits + (b*32)*8192 + co*256 + ph*128 + t;
    #pragma unroll
    for (int c = 0; c < 32; c++) {
        float lv = lgp[c*8192];
        l[c] = lv;
        float e = expf(lv - smaxs[c]);
        int r = __float2int_rn(__fmul_rn(__fdiv_rn(e, ssums[c]), 256.f));
        if (r) {
            #pragma unroll
            for (int no = 0; no < 8; no++)
                S[no] += r * (int)sv[(c*8 + no)*128 + t];
        }
    }
    float pq[8]; float ss = 0.f;
    #pragma unroll
    for (int no = 0; no < 8; no++) {
        float pre = __fadd_rn(__fmul_rn((float)S[no], 1.52587890625e-05f), sb[no]);
        float q = rintf(__fmul_rn(pre, 256.f)) * 0.00390625f;
        pq[no] = q; ss = __fadd_rn(ss, __fmul_rn(q, q));
    }
    float n   = sqrtf(ss);
    float den = __fadd_rn(1.f, __fmul_rn(n, n));
    int ai[8];
    #pragma unroll
    for (int no = 0; no < 8; no++) {
        float a = __fdiv_rn(__fmul_rn(pq[no], n), den);
        int q = __float2int_rn(__fmul_rn(a, 256.f));
        ai[no] = q;
        out[(bco*8 + no)*256 + ph*128 + t] = (float)q * 0.00390625f;
    }
    if (!last) {
        float* lw = g_logits + (b*32)*8192 + co*256 + ph*128 + t;
        #pragma unroll
        for (int c = 0; c < 32; c++) {
            int m = 0;
            #pragma unroll
            for (int no = 0; no < 8; no++)
                m += ai[no] * (int)sv[(c*8 + no)*128 + t];
            float lg = __fadd_rn(l[c], __fmul_rn((float)m, 1.52587890625e-05f));
            lw[c*8192] = rintf(__fmul_rn(lg, 256.f)) * 0.00390625f;
        }
    }
}

// ---------------------------------------------------------------------------
extern "C" void kernel_launch(void* const* d_in, const int* in_sizes, int n_in,
                              void* d_out, int out_size)
{
    const float* x    = (const float*)d_in[0];
    const float* w    = (const float*)d_in[1];
    const float* cb   = (const float*)d_in[2];
    const float* bias = (const float*)d_in[3];
    float* out = (float*)d_out;
    (void)in_sizes; (void)n_in; (void)out_size;

    const int ROUTE_SMEM = 65824;
    cudaFuncSetAttribute(conv_votes_kernel, cudaFuncAttributeMaxDynamicSharedMemorySize, CONV_SMEM);
    cudaFuncSetAttribute(route_kernel,      cudaFuncAttributeMaxDynamicSharedMemorySize, ROUTE_SMEM);

    prep_w_kernel<<<1, 256>>>(w);                                 // W -> fp16 hi/lo (layout-final)
    prep_x_kernel<<<1024, 256>>>(x);                              // x -> fp16 hi/lo (pre-im2col)
    conv_votes_kernel<<<1024, 512, CONV_SMEM>>>(cb, bias);        // + iteration 1 folded
    softmax_kernel<<<1024, 256>>>();                              // iteration 2
    route_kernel<<<2048, 128, ROUTE_SMEM>>>(bias, out, 0);
    softmax_kernel<<<1024, 256>>>();                              // iteration 3
    route_kernel<<<2048, 128, ROUTE_SMEM>>>(bias, out, 1);
}